// round 5
// baseline (speedup 1.0000x reference)
#include <cuda_runtime.h>
#include <cuda_bf16.h>
#include <cstdint>
#include <math.h>

#define DIM   512
#define CDIM  128
#define CSIZE 8192
#define MMAX  16384
#define EPSV  1e-6f
#define CAP   64

// ---- dist kernel tiling ----
#define MT 128
#define NT 256
#define KC 32
#define NSTAGES (DIM / KC)        // 16
#define NBUF 4
#define ROWB 80                   // 32 bf16 = 64B + 16B pad
#define OFF_B (128 * ROWB)        // A: 128 rows, B: 256 rows
#define SM_STAGE (384 * ROWB)     // 30720
#define SM_BUF0 1024              // cc tile first
#define SM_TOTAL (SM_BUF0 + NBUF * SM_STAGE)   // 123904

// ---------------- device scratch ----------------
__device__ float g_h[CSIZE * DIM];
__device__ float g_icb[CSIZE * DIM];
__device__ float g_cc[CSIZE];
__device__ float g_ccpart[4 * CSIZE];
__device__ float g_xx[MMAX];
__device__ float g_rowloss[MMAX];
__device__ __nv_bfloat16 g_xhi[MMAX * DIM];
__device__ __nv_bfloat16 g_chi[CSIZE * DIM];
__device__ unsigned int g_rowmin[MMAX];
__device__ unsigned int g_ccount[MMAX];
__device__ int g_cand[MMAX * CAP];
__device__ unsigned int g_maxcc_u;

// ---------------- helpers ----------------
__device__ __forceinline__ uint32_t smem_u32(const void* p) {
    uint32_t a;
    asm("{ .reg .u64 t; cvta.to.shared.u64 t, %1; cvt.u32.u64 %0, t; }"
        : "=r"(a) : "l"(p));
    return a;
}

#define CP_ASYNC16(dst, src) \
    asm volatile("cp.async.cg.shared.global [%0], [%1], 16;" :: "r"(dst), "l"(src))
#define CP_COMMIT() asm volatile("cp.async.commit_group;" ::: "memory")
#define CP_WAIT2() asm volatile("cp.async.wait_group 2;" ::: "memory")

__device__ __forceinline__ void ldm_x4(uint32_t* r, uint32_t addr) {
    asm volatile("ldmatrix.sync.aligned.m8n8.x4.shared.b16 {%0,%1,%2,%3}, [%4];"
                 : "=r"(r[0]), "=r"(r[1]), "=r"(r[2]), "=r"(r[3]) : "r"(addr));
}
__device__ __forceinline__ void ldm_x2(uint32_t* r, uint32_t addr) {
    asm volatile("ldmatrix.sync.aligned.m8n8.x2.shared.b16 {%0,%1}, [%2];"
                 : "=r"(r[0]), "=r"(r[1]) : "r"(addr));
}
__device__ __forceinline__ void mma_bf16(float* c, const uint32_t* a, const uint32_t* b) {
    asm volatile(
        "mma.sync.aligned.m16n8k16.row.col.f32.bf16.bf16.f32 "
        "{%0,%1,%2,%3}, {%4,%5,%6,%7}, {%8,%9}, {%0,%1,%2,%3};"
        : "+f"(c[0]), "+f"(c[1]), "+f"(c[2]), "+f"(c[3])
        : "r"(a[0]), "r"(a[1]), "r"(a[2]), "r"(a[3]), "r"(b[0]), "r"(b[1]));
}

__device__ __forceinline__ unsigned int ord_enc(float f) {
    unsigned int u = __float_as_uint(f);
    return (u & 0x80000000u) ? ~u : (u | 0x80000000u);
}
__device__ __forceinline__ float ord_dec(unsigned int e) {
    unsigned int u = (e & 0x80000000u) ? (e & 0x7fffffffu) : ~e;
    return __uint_as_float(u);
}

__device__ __forceinline__ float selu_f(float z) {
    const float a = 1.6732632423543772f;
    const float s = 1.0507009873554805f;
    return s * (z > 0.f ? z : a * expm1f(z));
}

// ---------------- prep_x: xx + xhi + init state ----------------
__global__ void prep_x_k(const float* __restrict__ X) {
    int m = blockIdx.x;
    int tid = threadIdx.x;     // 128
    const float* r = X + (size_t)m * DIM;
    __nv_bfloat16* ho = g_xhi + (size_t)m * DIM;
    float s = 0.f;
#pragma unroll
    for (int i = 0; i < 4; i++) {
        float v = r[tid + i * 128];
        s += v * v;
        ho[tid + i * 128] = __float2bfloat16(v);
    }
    for (int o = 16; o > 0; o >>= 1) s += __shfl_down_sync(0xffffffffu, s, o);
    __shared__ float sb[4];
    if ((tid & 31) == 0) sb[tid >> 5] = s;
    __syncthreads();
    if (tid == 0) {
        g_xx[m] = sb[0] + sb[1] + sb[2] + sb[3];
        g_rowmin[m] = 0xFFFFFFFFu;
        g_ccount[m] = 0u;
        if (m == 0) g_maxcc_u = 0u;
    }
}

// ---------------- 64x128 SGEMM: C = f(A)@B + bias (+ Ares) [+bf16 +cc] ------
__global__ void __launch_bounds__(256) gemm64x128_k(
    const float* __restrict__ A, const float* __restrict__ B,
    const float* __restrict__ bias, const float* __restrict__ Ares,
    float* __restrict__ C, int M, int N, int K, int doSelu,
    __nv_bfloat16* __restrict__ hiOut, float* __restrict__ ccpart)
{
    __shared__ float As[16][66];
    __shared__ float Bs[16][128];
    int tid = threadIdx.x;
    int tx = tid & 15, ty = tid >> 4;
    int m0 = blockIdx.y * 64, n0 = blockIdx.x * 128;

    int arow = tid >> 2, ak = (tid & 3) * 4;   // 64 rows x 16 k
    int brow = tid >> 4, bcol = (tid & 15) * 8;

    float acc[4][8];
#pragma unroll
    for (int i = 0; i < 4; i++)
#pragma unroll
        for (int j = 0; j < 8; j++) acc[i][j] = 0.f;

    for (int k0 = 0; k0 < K; k0 += 16) {
        float4 av = *(const float4*)(A + (size_t)(m0 + arow) * K + k0 + ak);
        if (doSelu) {
            av.x = selu_f(av.x); av.y = selu_f(av.y);
            av.z = selu_f(av.z); av.w = selu_f(av.w);
        }
        As[ak + 0][arow] = av.x; As[ak + 1][arow] = av.y;
        As[ak + 2][arow] = av.z; As[ak + 3][arow] = av.w;

        float4 b0 = *(const float4*)(B + (size_t)(k0 + brow) * N + n0 + bcol);
        float4 b1 = *(const float4*)(B + (size_t)(k0 + brow) * N + n0 + bcol + 4);
        *(float4*)&Bs[brow][bcol] = b0;
        *(float4*)&Bs[brow][bcol + 4] = b1;
        __syncthreads();

#pragma unroll
        for (int k = 0; k < 16; k++) {
            float a[4], b[8];
#pragma unroll
            for (int i = 0; i < 4; i++) a[i] = As[k][ty * 4 + i];
#pragma unroll
            for (int j = 0; j < 8; j++) b[j] = Bs[k][tx * 8 + j];
#pragma unroll
            for (int i = 0; i < 4; i++)
#pragma unroll
                for (int j = 0; j < 8; j++) acc[i][j] += a[i] * b[j];
        }
        __syncthreads();
    }

    int part = n0 >> 7;
#pragma unroll
    for (int i = 0; i < 4; i++) {
        int m = m0 + ty * 4 + i;
        float s = 0.f;
#pragma unroll
        for (int j = 0; j < 8; j++) {
            int n = n0 + tx * 8 + j;
            float v = acc[i][j] + bias[n];
            if (Ares) v += Ares[(size_t)m * N + n];
            C[(size_t)m * N + n] = v;
            if (hiOut) hiOut[(size_t)m * N + n] = __float2bfloat16(v);
            s += v * v;
        }
        if (ccpart) {
#pragma unroll
            for (int o = 8; o > 0; o >>= 1)
                s += __shfl_down_sync(0xffffffffu, s, o, 16);
            if (tx == 0) ccpart[part * CSIZE + m] = s;
        }
    }
}

// ---------------- cc finalize: sum 4 parts + global max ----------------
__global__ void ccfin_k() {
    int i = blockIdx.x * 256 + threadIdx.x;
    float cc = ((g_ccpart[i] + g_ccpart[CSIZE + i]) + g_ccpart[2 * CSIZE + i])
               + g_ccpart[3 * CSIZE + i];
    g_cc[i] = cc;
    float mx = cc;
    for (int o = 16; o > 0; o >>= 1) mx = fmaxf(mx, __shfl_down_sync(0xffffffffu, mx, o));
    __shared__ float sb[8];
    int tid = threadIdx.x;
    if ((tid & 31) == 0) sb[tid >> 5] = mx;
    __syncthreads();
    if (tid == 0) {
        float t = sb[0];
#pragma unroll
        for (int k = 1; k < 8; k++) t = fmaxf(t, sb[k]);
        atomicMax(&g_maxcc_u, ord_enc(t));
    }
}

// ---------------- Phase 1: approx bf16 dist GEMM + candidate filter --------
// CTA tile 128x256, 8 warps of 64x64, 4-stage cp.async pipeline.
__global__ void __launch_bounds__(256, 1) dist_mma_k() {
    extern __shared__ char smem[];
    uint32_t sbase = smem_u32(smem);
    float* s_cc = (float*)smem;

    int tid = threadIdx.x;
    int wid = tid >> 5, lane = tid & 31;
    int bn = blockIdx.x * NT;
    int bm = blockIdx.y * MT;

    int wm = (wid & 1) * 64;
    int wn = (wid >> 1) * 64;

    s_cc[tid] = g_cc[bn + tid];
    float maxcc = ord_dec(g_maxcc_u);

    float acc[4][8][4];
#pragma unroll
    for (int i = 0; i < 4; i++)
#pragma unroll
        for (int j = 0; j < 8; j++)
#pragma unroll
            for (int r = 0; r < 4; r++) acc[i][j][r] = 0.f;

    auto issue_stage = [&](int s) {
        int k0 = s * KC;
        uint32_t buf = sbase + SM_BUF0 + (uint32_t)(s & 3) * SM_STAGE;
#pragma unroll
        for (int r = 0; r < 2; r++) {          // A: 512 chunks
            int c = tid + 256 * r;
            int row = c >> 2, p = c & 3;
            CP_ASYNC16(buf + (uint32_t)(row * ROWB + p * 16),
                       g_xhi + (size_t)(bm + row) * DIM + k0 + p * 8);
        }
#pragma unroll
        for (int r = 0; r < 4; r++) {          // B: 1024 chunks
            int c = tid + 256 * r;
            int row = c >> 2, p = c & 3;
            CP_ASYNC16(buf + OFF_B + (uint32_t)(row * ROWB + p * 16),
                       g_chi + (size_t)(bn + row) * DIM + k0 + p * 8);
        }
    };

    issue_stage(0); CP_COMMIT();
    issue_stage(1); CP_COMMIT();
    issue_stage(2); CP_COMMIT();

    for (int s = 0; s < NSTAGES; s++) {
        CP_WAIT2();
        __syncthreads();
        if (s + 3 < NSTAGES) { issue_stage(s + 3); CP_COMMIT(); }

        uint32_t buf = sbase + SM_BUF0 + (uint32_t)(s & 3) * SM_STAGE;
#pragma unroll
        for (int kk = 0; kk < 2; kk++) {
            int kb = kk * 32;
            uint32_t a[4][4];
#pragma unroll
            for (int im = 0; im < 4; im++)
                ldm_x4(a[im], buf + (uint32_t)((wm + im * 16 + (lane & 15)) * ROWB
                                               + kb + (lane >> 4) * 16));
#pragma unroll
            for (int j = 0; j < 8; j++) {
                uint32_t b[2];
                ldm_x2(b, buf + OFF_B + (uint32_t)((wn + j * 8 + (lane & 7)) * ROWB
                                                   + kb + ((lane >> 3) & 1) * 16));
#pragma unroll
                for (int im = 0; im < 4; im++) mma_bf16(acc[im][j], a[im], b);
            }
        }
    }

    // -------- epilogue: approx d2, running rowmin, candidate push --------
    int q = lane >> 2, t = lane & 3;
#pragma unroll
    for (int im = 0; im < 4; im++) {
#pragma unroll
        for (int h = 0; h < 2; h++) {
            int row = bm + wm + im * 16 + h * 8 + q;
            float xxv = g_xx[row];
            float d2s[16];
            float best = 3.4e38f;
#pragma unroll
            for (int j = 0; j < 8; j++) {
#pragma unroll
                for (int e = 0; e < 2; e++) {
                    float dot = acc[im][j][h * 2 + e];
                    float d2 = __fadd_rn(__fadd_rn(xxv, __fmul_rn(dot, -2.0f)),
                                         s_cc[wn + j * 8 + 2 * t + e]);
                    d2s[j * 2 + e] = d2;
                    best = fminf(best, d2);
                }
            }
            unsigned int fb = ord_enc(best);
            unsigned int o1 = __shfl_xor_sync(0xffffffffu, fb, 1);
            fb = (o1 < fb) ? o1 : fb;
            unsigned int o2 = __shfl_xor_sync(0xffffffffu, fb, 2);
            fb = (o2 < fb) ? o2 : fb;
            unsigned int old = 0xFFFFFFFFu;
            if (t == 0) old = atomicMin(&g_rowmin[row], fb);
            old = __shfl_sync(0xffffffffu, old, lane & ~3);
            unsigned int run = (old < fb) ? old : fb;
            float thr = ord_dec(run) + (2.f * sqrtf(xxv * maxcc) * 0.0078125f + 0.01f);
#pragma unroll
            for (int j = 0; j < 8; j++) {
#pragma unroll
                for (int e = 0; e < 2; e++) {
                    if (d2s[j * 2 + e] < thr) {
                        unsigned int slot = atomicAdd(&g_ccount[row], 1u);
                        if (slot < CAP)
                            g_cand[row * CAP + slot] = bn + wn + j * 8 + 2 * t + e;
                    }
                }
            }
        }
    }
}

// ---------------- Phase 2 + finish: exact refine, rotation, loss -----------
__global__ void refine_finish_k(const float* __restrict__ X, float* __restrict__ out,
                                int M, long long idx_off)
{
    int m = blockIdx.x;
    int tid = threadIdx.x;   // 128
    unsigned int cnt = g_ccount[m];
    float xxv = g_xx[m];
    const float* xr = X + (size_t)m * DIM;

    float xv[4];
#pragma unroll
    for (int i = 0; i < 4; i++) xv[i] = xr[tid + i * 128];

    __shared__ float sred[4];
    __shared__ unsigned long long s_best;
    __shared__ int s_idx;
    if (tid == 0) s_best = ~0ULL;
    __syncthreads();

    bool fullscan = (cnt == 0u) || (cnt > (unsigned)CAP);
    int n_iter = fullscan ? CSIZE : (int)cnt;

    for (int s = 0; s < n_iter; s++) {
        int c = fullscan ? s : g_cand[m * CAP + s];
        const float* cr = g_icb + (size_t)c * DIM;
        float p = 0.f;
#pragma unroll
        for (int i = 0; i < 4; i++) p += xv[i] * cr[tid + i * 128];
        for (int o = 16; o > 0; o >>= 1) p += __shfl_down_sync(0xffffffffu, p, o);
        if ((tid & 31) == 0) sred[tid >> 5] = p;
        __syncthreads();
        if (tid == 0) {
            float dot = sred[0] + sred[1] + sred[2] + sred[3];
            float d2 = __fadd_rn(__fadd_rn(xxv, __fmul_rn(dot, -2.0f)), g_cc[c]);
            unsigned long long key =
                ((unsigned long long)ord_enc(d2) << 32) | (unsigned)c;
            if (key < s_best) s_best = key;
        }
        __syncthreads();
    }
    if (tid == 0) s_idx = (int)(s_best & 0xffffffffu);
    __syncthreads();
    int idx = s_idx;

    // ---- rotation + loss (identical arithmetic to round 4) ----
    const float* qr = g_icb + (size_t)idx * DIM;
    float qv[4];
    float sx2 = 0.f, sq2 = 0.f, sd2 = 0.f;
#pragma unroll
    for (int i = 0; i < 4; i++) {
        int d = tid + i * 128;
        qv[i] = qr[d];
        sx2 += xv[i] * xv[i];
        sq2 += qv[i] * qv[i];
        float df = xv[i] - qv[i];
        sd2 += df * df;
    }

    __shared__ float sb[16];
    {
        float v0 = sx2, v1 = sq2, v2 = sd2;
        for (int o = 16; o > 0; o >>= 1) {
            v0 += __shfl_down_sync(0xffffffffu, v0, o);
            v1 += __shfl_down_sync(0xffffffffu, v1, o);
            v2 += __shfl_down_sync(0xffffffffu, v2, o);
        }
        int w = tid >> 5;
        if ((tid & 31) == 0) { sb[w] = v0; sb[4 + w] = v1; sb[8 + w] = v2; }
        __syncthreads();
        sx2 = sb[0] + sb[1] + sb[2] + sb[3];
        sq2 = sb[4] + sb[5] + sb[6] + sb[7];
        sd2 = sb[8] + sb[9] + sb[10] + sb[11];
        __syncthreads();
    }

    float ns = sqrtf(sx2), nt = sqrtf(sq2);
    float ins = 1.f / fmaxf(ns, EPSV);
    float inv_t = 1.f / fmaxf(nt, EPSV);

    float wv[4];
    float sw2 = 0.f, sxw = 0.f;
#pragma unroll
    for (int i = 0; i < 4; i++) {
        float w = xv[i] * ins + qv[i] * inv_t;
        wv[i] = w;
        sw2 += w * w;
        sxw += xv[i] * w;
    }
    {
        float v0 = sw2, v1 = sxw;
        for (int o = 16; o > 0; o >>= 1) {
            v0 += __shfl_down_sync(0xffffffffu, v0, o);
            v1 += __shfl_down_sync(0xffffffffu, v1, o);
        }
        int w = tid >> 5;
        if ((tid & 31) == 0) { sb[w] = v0; sb[4 + w] = v1; }
        __syncthreads();
        sw2 = sb[0] + sb[1] + sb[2] + sb[3];
        sxw = sb[4] + sb[5] + sb[6] + sb[7];
        __syncthreads();
    }

    float iwn = 1.f / fmaxf(sqrtf(sw2), EPSV);
    float xdw = sxw * iwn;
    float xdu = sx2 * ins;
    float scl = nt * ins;

    float* orow = out + (size_t)m * DIM;
#pragma unroll
    for (int i = 0; i < 4; i++) {
        int d = tid + i * 128;
        float r = xv[i] - 2.f * xdw * (wv[i] * iwn) + 2.f * xdu * (qv[i] * inv_t);
        orow[d] = r * scl;
    }

    if (tid == 0) {
        g_rowloss[m] = sd2;
        if (idx_off >= 0) out[idx_off + m] = (float)idx;
    }
}

__global__ void loss_k(float* __restrict__ out, int M, long long pos) {
    int tid = threadIdx.x;
    float s = 0.f;
    for (int i = tid; i < M; i += 256) s += g_rowloss[i];
    for (int o = 16; o > 0; o >>= 1) s += __shfl_down_sync(0xffffffffu, s, o);
    __shared__ float sb[8];
    if ((tid & 31) == 0) sb[tid >> 5] = s;
    __syncthreads();
    if (tid == 0) {
        float t = 0.f;
        for (int i = 0; i < 8; i++) t += sb[i];
        if (pos >= 0) out[pos] = 1.25f * t / (float)((size_t)M * DIM);
    }
}

// ---------------- host launcher ----------------
extern "C" void kernel_launch(void* const* d_in, const int* in_sizes, int n_in,
                              void* d_out, int out_size)
{
    const float* x  = (const float*)d_in[0];
    const float* cb = (const float*)d_in[1];
    const float* W1 = (const float*)d_in[2];
    const float* b1 = (const float*)d_in[3];
    const float* W2 = (const float*)d_in[4];
    const float* b2 = (const float*)d_in[5];
    float* out = (float*)d_out;

    int M = in_sizes[0] / DIM;
    long long NQ = (long long)M * DIM;

    long long idx_off = (out_size >= NQ + M) ? NQ : -1;
    long long loss_pos = -1;
    if (out_size >= NQ + M + 1) loss_pos = NQ + M;
    else if (out_size == NQ + 1) loss_pos = NQ;

    float *p_h, *p_icb, *p_ccpart;
    __nv_bfloat16 *p_chi;
    cudaGetSymbolAddress((void**)&p_h,      g_h);
    cudaGetSymbolAddress((void**)&p_icb,    g_icb);
    cudaGetSymbolAddress((void**)&p_ccpart, g_ccpart);
    cudaGetSymbolAddress((void**)&p_chi,    g_chi);

    cudaFuncSetAttribute(dist_mma_k, cudaFuncAttributeMaxDynamicSharedMemorySize, SM_TOTAL);

    cudaMemsetAsync(d_out, 0, (size_t)out_size * sizeof(float));

    // x prep (xx, xhi, state init)
    prep_x_k<<<M, 128>>>(x);

    // icb transform (fp32, fused bf16 + ||.||^2 epilogue on pass 2)
    gemm64x128_k<<<dim3(DIM / 128, CSIZE / 64), 256>>>(
        cb, W1, b1, nullptr, p_h, CSIZE, DIM, CDIM, 0, nullptr, nullptr);
    gemm64x128_k<<<dim3(DIM / 128, CSIZE / 64), 256>>>(
        p_h, W2, b2, p_h, p_icb, CSIZE, DIM, DIM, 1, p_chi, p_ccpart);
    ccfin_k<<<CSIZE / 256, 256>>>();

    // phase 1: approx distances + candidates
    dist_mma_k<<<dim3(CSIZE / NT, M / MT), 256, SM_TOTAL>>>();

    // phase 2 + finish
    refine_finish_k<<<M, 128>>>(x, out, M, idx_off);
    loss_k<<<1, 256>>>(out, M, loss_pos);
}

// round 6
// speedup vs baseline: 1.1831x; 1.1831x over previous
#include <cuda_runtime.h>
#include <cuda_bf16.h>
#include <cstdint>
#include <math.h>

#define DIM   512
#define CDIM  128
#define CSIZE 8192
#define MMAX  16384
#define EPSV  1e-6f
#define CAP   64

// ---- dist kernel tiling (round-4 proven config) ----
#define MT 128
#define NT 128
#define KC 32
#define NSTAGES (DIM / KC)        // 16
#define ROWB 80                   // 32 bf16 = 64B + 16B pad
#define BUFSZ (128 * ROWB)        // 10240 B
#define OFF_AHI 0
#define OFF_BHI BUFSZ
#define SM_STAGE (2 * BUFSZ)      // 20480
#define SM_BUF0 1024              // cc tile
#define SM_TOTAL (SM_BUF0 + 2 * SM_STAGE)   // 41984

// ---------------- device scratch ----------------
__device__ float g_h[CSIZE * DIM];
__device__ float g_icb[CSIZE * DIM];
__device__ float g_cc[CSIZE];
__device__ float g_ccpart[4 * CSIZE];
__device__ float g_xx[MMAX];
__device__ float g_rowloss[MMAX];
__device__ __nv_bfloat16 g_xhi[MMAX * DIM];
__device__ __nv_bfloat16 g_chi[CSIZE * DIM];
__device__ unsigned int g_rowmin[MMAX];
__device__ unsigned int g_ccount[MMAX];
__device__ int g_cand[MMAX * CAP];
__device__ unsigned int g_maxcc_u;

// ---------------- helpers ----------------
__device__ __forceinline__ uint32_t smem_u32(const void* p) {
    uint32_t a;
    asm("{ .reg .u64 t; cvta.to.shared.u64 t, %1; cvt.u32.u64 %0, t; }"
        : "=r"(a) : "l"(p));
    return a;
}

#define CP_ASYNC16(dst, src) \
    asm volatile("cp.async.cg.shared.global [%0], [%1], 16;" :: "r"(dst), "l"(src))
#define CP_COMMIT() asm volatile("cp.async.commit_group;" ::: "memory")
#define CP_WAIT1() asm volatile("cp.async.wait_group 1;" ::: "memory")
#define CP_WAIT0() asm volatile("cp.async.wait_group 0;" ::: "memory")

__device__ __forceinline__ void ldm_x4(uint32_t* r, uint32_t addr) {
    asm volatile("ldmatrix.sync.aligned.m8n8.x4.shared.b16 {%0,%1,%2,%3}, [%4];"
                 : "=r"(r[0]), "=r"(r[1]), "=r"(r[2]), "=r"(r[3]) : "r"(addr));
}
__device__ __forceinline__ void ldm_x2(uint32_t* r, uint32_t addr) {
    asm volatile("ldmatrix.sync.aligned.m8n8.x2.shared.b16 {%0,%1}, [%2];"
                 : "=r"(r[0]), "=r"(r[1]) : "r"(addr));
}
__device__ __forceinline__ void mma_bf16(float* c, const uint32_t* a, const uint32_t* b) {
    asm volatile(
        "mma.sync.aligned.m16n8k16.row.col.f32.bf16.bf16.f32 "
        "{%0,%1,%2,%3}, {%4,%5,%6,%7}, {%8,%9}, {%0,%1,%2,%3};"
        : "+f"(c[0]), "+f"(c[1]), "+f"(c[2]), "+f"(c[3])
        : "r"(a[0]), "r"(a[1]), "r"(a[2]), "r"(a[3]), "r"(b[0]), "r"(b[1]));
}

__device__ __forceinline__ unsigned int ord_enc(float f) {
    unsigned int u = __float_as_uint(f);
    return (u & 0x80000000u) ? ~u : (u | 0x80000000u);
}
__device__ __forceinline__ float ord_dec(unsigned int e) {
    unsigned int u = (e & 0x80000000u) ? (e & 0x7fffffffu) : ~e;
    return __uint_as_float(u);
}

__device__ __forceinline__ float selu_f(float z) {
    const float a = 1.6732632423543772f;
    const float s = 1.0507009873554805f;
    return s * (z > 0.f ? z : a * expm1f(z));
}

// ---------------- prep_x: xx + xhi + init state ----------------
__global__ void prep_x_k(const float* __restrict__ X) {
    int m = blockIdx.x;
    int tid = threadIdx.x;     // 128
    const float* r = X + (size_t)m * DIM;
    __nv_bfloat16* ho = g_xhi + (size_t)m * DIM;
    float s = 0.f;
#pragma unroll
    for (int i = 0; i < 4; i++) {
        float v = r[tid + i * 128];
        s += v * v;
        ho[tid + i * 128] = __float2bfloat16(v);
    }
    for (int o = 16; o > 0; o >>= 1) s += __shfl_down_sync(0xffffffffu, s, o);
    __shared__ float sb[4];
    if ((tid & 31) == 0) sb[tid >> 5] = s;
    __syncthreads();
    if (tid == 0) {
        g_xx[m] = sb[0] + sb[1] + sb[2] + sb[3];
        g_rowmin[m] = 0xFFFFFFFFu;
        g_ccount[m] = 0u;
        if (m == 0) g_maxcc_u = 0u;
    }
}

// ---------------- 64x128 SGEMM: C = f(A)@B + bias (+ Ares) [+bf16 +cc] ------
__global__ void __launch_bounds__(256) gemm64x128_k(
    const float* __restrict__ A, const float* __restrict__ B,
    const float* __restrict__ bias, const float* __restrict__ Ares,
    float* __restrict__ C, int M, int N, int K, int doSelu,
    __nv_bfloat16* __restrict__ hiOut, float* __restrict__ ccpart)
{
    __shared__ float As[16][66];
    __shared__ float Bs[16][128];
    int tid = threadIdx.x;
    int tx = tid & 15, ty = tid >> 4;
    int m0 = blockIdx.y * 64, n0 = blockIdx.x * 128;

    int arow = tid >> 2, ak = (tid & 3) * 4;   // 64 rows x 16 k
    int brow = tid >> 4, bcol = (tid & 15) * 8;

    float acc[4][8];
#pragma unroll
    for (int i = 0; i < 4; i++)
#pragma unroll
        for (int j = 0; j < 8; j++) acc[i][j] = 0.f;

    for (int k0 = 0; k0 < K; k0 += 16) {
        float4 av = *(const float4*)(A + (size_t)(m0 + arow) * K + k0 + ak);
        if (doSelu) {
            av.x = selu_f(av.x); av.y = selu_f(av.y);
            av.z = selu_f(av.z); av.w = selu_f(av.w);
        }
        As[ak + 0][arow] = av.x; As[ak + 1][arow] = av.y;
        As[ak + 2][arow] = av.z; As[ak + 3][arow] = av.w;

        float4 b0 = *(const float4*)(B + (size_t)(k0 + brow) * N + n0 + bcol);
        float4 b1 = *(const float4*)(B + (size_t)(k0 + brow) * N + n0 + bcol + 4);
        *(float4*)&Bs[brow][bcol] = b0;
        *(float4*)&Bs[brow][bcol + 4] = b1;
        __syncthreads();

#pragma unroll
        for (int k = 0; k < 16; k++) {
            float a[4], b[8];
#pragma unroll
            for (int i = 0; i < 4; i++) a[i] = As[k][ty * 4 + i];
#pragma unroll
            for (int j = 0; j < 8; j++) b[j] = Bs[k][tx * 8 + j];
#pragma unroll
            for (int i = 0; i < 4; i++)
#pragma unroll
                for (int j = 0; j < 8; j++) acc[i][j] += a[i] * b[j];
        }
        __syncthreads();
    }

    int part = n0 >> 7;
#pragma unroll
    for (int i = 0; i < 4; i++) {
        int m = m0 + ty * 4 + i;
        float s = 0.f;
#pragma unroll
        for (int j = 0; j < 8; j++) {
            int n = n0 + tx * 8 + j;
            float v = acc[i][j] + bias[n];
            if (Ares) v += Ares[(size_t)m * N + n];
            C[(size_t)m * N + n] = v;
            if (hiOut) hiOut[(size_t)m * N + n] = __float2bfloat16(v);
            s += v * v;
        }
        if (ccpart) {
#pragma unroll
            for (int o = 8; o > 0; o >>= 1)
                s += __shfl_down_sync(0xffffffffu, s, o, 16);
            if (tx == 0) ccpart[part * CSIZE + m] = s;
        }
    }
}

// ---------------- cc finalize: sum 4 parts + global max ----------------
__global__ void ccfin_k() {
    int i = blockIdx.x * 256 + threadIdx.x;
    float cc = ((g_ccpart[i] + g_ccpart[CSIZE + i]) + g_ccpart[2 * CSIZE + i])
               + g_ccpart[3 * CSIZE + i];
    g_cc[i] = cc;
    float mx = cc;
    for (int o = 16; o > 0; o >>= 1) mx = fmaxf(mx, __shfl_down_sync(0xffffffffu, mx, o));
    __shared__ float sb[8];
    int tid = threadIdx.x;
    if ((tid & 31) == 0) sb[tid >> 5] = mx;
    __syncthreads();
    if (tid == 0) {
        float t = sb[0];
#pragma unroll
        for (int k = 1; k < 8; k++) t = fmaxf(t, sb[k]);
        atomicMax(&g_maxcc_u, ord_enc(t));
    }
}

// ---------------- Phase 1: approx bf16 dist GEMM + candidate filter --------
// Round-4 proven config: CTA 128x128, 8 warps of 32x64, 2-stage pipeline.
__global__ void __launch_bounds__(256) dist_mma_k() {
    extern __shared__ char smem[];
    uint32_t sbase = smem_u32(smem);
    float* s_cc = (float*)smem;

    int tid = threadIdx.x;
    int wid = tid >> 5, lane = tid & 31;
    int bn = blockIdx.x * NT;
    int bm = blockIdx.y * MT;

    int wm = (wid & 3) * 32;
    int wn = (wid >> 2) * 64;

    if (tid < NT) s_cc[tid] = g_cc[bn + tid];
    float maxcc = ord_dec(g_maxcc_u);

    float acc[2][8][4];
#pragma unroll
    for (int i = 0; i < 2; i++)
#pragma unroll
        for (int j = 0; j < 8; j++)
#pragma unroll
            for (int r = 0; r < 4; r++) acc[i][j][r] = 0.f;

    const __nv_bfloat16* xhi = g_xhi;
    const __nv_bfloat16* chi = g_chi;

    auto issue_stage = [&](int s) {
        int b = s & 1;
        int k0 = s * KC;
        uint32_t buf = sbase + SM_BUF0 + b * SM_STAGE;
#pragma unroll
        for (int r = 0; r < 2; r++) {
            int c = tid + 256 * r;
            int row = c >> 2, part = c & 3;
            uint32_t so = (uint32_t)(row * ROWB + part * 16);
            size_t goA = (size_t)(bm + row) * DIM + k0 + part * 8;
            size_t goB = (size_t)(bn + row) * DIM + k0 + part * 8;
            CP_ASYNC16(buf + OFF_AHI + so, xhi + goA);
            CP_ASYNC16(buf + OFF_BHI + so, chi + goB);
        }
    };

    issue_stage(0);
    CP_COMMIT();

    for (int s = 0; s < NSTAGES; s++) {
        if (s + 1 < NSTAGES) {
            issue_stage(s + 1);
            CP_COMMIT();
            CP_WAIT1();
        } else {
            CP_WAIT0();
        }
        __syncthreads();

        uint32_t buf = sbase + SM_BUF0 + (s & 1) * SM_STAGE;
#pragma unroll
        for (int kk = 0; kk < 2; kk++) {
            int kb = kk * 32;
            uint32_t arow = (uint32_t)((wm + (lane & 15)) * ROWB + kb + (lane >> 4) * 16);
            uint32_t ahi0[4], ahi1[4];
            ldm_x4(ahi0, buf + OFF_AHI + arow);
            ldm_x4(ahi1, buf + OFF_AHI + arow + 16 * ROWB);

            uint32_t brow_base =
                (uint32_t)((wn + (lane & 7)) * ROWB + kb + ((lane >> 3) & 1) * 16);
#pragma unroll
            for (int j = 0; j < 8; j++) {
                uint32_t bo = brow_base + (uint32_t)(j * 8 * ROWB);
                uint32_t bhi[2];
                ldm_x2(bhi, buf + OFF_BHI + bo);
                mma_bf16(acc[0][j], ahi0, bhi);
                mma_bf16(acc[1][j], ahi1, bhi);
            }
        }
        __syncthreads();
    }

    // -------- epilogue: approx d2, running rowmin, candidate push --------
    int q = lane >> 2, t = lane & 3;
#pragma unroll
    for (int i = 0; i < 2; i++) {
#pragma unroll
        for (int h = 0; h < 2; h++) {
            int row = bm + wm + i * 16 + h * 8 + q;
            float xxv = g_xx[row];
            float d2s[16];
            float best = 3.4e38f;
#pragma unroll
            for (int j = 0; j < 8; j++) {
#pragma unroll
                for (int e = 0; e < 2; e++) {
                    float dot = acc[i][j][h * 2 + e];
                    float d2 = __fadd_rn(__fadd_rn(xxv, __fmul_rn(dot, -2.0f)),
                                         s_cc[wn + j * 8 + 2 * t + e]);
                    d2s[j * 2 + e] = d2;
                    best = fminf(best, d2);
                }
            }
            unsigned int fb = ord_enc(best);
            unsigned int o1 = __shfl_xor_sync(0xffffffffu, fb, 1);
            fb = (o1 < fb) ? o1 : fb;
            unsigned int o2 = __shfl_xor_sync(0xffffffffu, fb, 2);
            fb = (o2 < fb) ? o2 : fb;
            unsigned int old = 0xFFFFFFFFu;
            if (t == 0) old = atomicMin(&g_rowmin[row], fb);
            old = __shfl_sync(0xffffffffu, old, lane & ~3);
            unsigned int run = (old < fb) ? old : fb;
            float thr = ord_dec(run) + (2.f * sqrtf(xxv * maxcc) * 0.0078125f + 0.01f);
#pragma unroll
            for (int j = 0; j < 8; j++) {
#pragma unroll
                for (int e = 0; e < 2; e++) {
                    if (d2s[j * 2 + e] < thr) {
                        unsigned int slot = atomicAdd(&g_ccount[row], 1u);
                        if (slot < CAP)
                            g_cand[row * CAP + slot] = bn + wn + j * 8 + 2 * t + e;
                    }
                }
            }
        }
    }
}

// ---------------- Phase 2 + finish: exact refine, rotation, loss -----------
__global__ void refine_finish_k(const float* __restrict__ X, float* __restrict__ out,
                                int M, long long idx_off)
{
    int m = blockIdx.x;
    int tid = threadIdx.x;   // 128
    unsigned int cnt = g_ccount[m];
    float xxv = g_xx[m];
    const float* xr = X + (size_t)m * DIM;

    float xv[4];
#pragma unroll
    for (int i = 0; i < 4; i++) xv[i] = xr[tid + i * 128];

    __shared__ float sred[4];
    __shared__ unsigned long long s_best;
    __shared__ int s_idx;
    if (tid == 0) s_best = ~0ULL;
    __syncthreads();

    bool fullscan = (cnt == 0u) || (cnt > (unsigned)CAP);
    int n_iter = fullscan ? CSIZE : (int)cnt;

    for (int s = 0; s < n_iter; s++) {
        int c = fullscan ? s : g_cand[m * CAP + s];
        const float* cr = g_icb + (size_t)c * DIM;
        float p = 0.f;
#pragma unroll
        for (int i = 0; i < 4; i++) p += xv[i] * cr[tid + i * 128];
        for (int o = 16; o > 0; o >>= 1) p += __shfl_down_sync(0xffffffffu, p, o);
        if ((tid & 31) == 0) sred[tid >> 5] = p;
        __syncthreads();
        if (tid == 0) {
            float dot = sred[0] + sred[1] + sred[2] + sred[3];
            float d2 = __fadd_rn(__fadd_rn(xxv, __fmul_rn(dot, -2.0f)), g_cc[c]);
            unsigned long long key =
                ((unsigned long long)ord_enc(d2) << 32) | (unsigned)c;
            if (key < s_best) s_best = key;
        }
        __syncthreads();
    }
    if (tid == 0) s_idx = (int)(s_best & 0xffffffffu);
    __syncthreads();
    int idx = s_idx;

    // ---- rotation + loss ----
    const float* qr = g_icb + (size_t)idx * DIM;
    float qv[4];
    float sx2 = 0.f, sq2 = 0.f, sd2 = 0.f;
#pragma unroll
    for (int i = 0; i < 4; i++) {
        int d = tid + i * 128;
        qv[i] = qr[d];
        sx2 += xv[i] * xv[i];
        sq2 += qv[i] * qv[i];
        float df = xv[i] - qv[i];
        sd2 += df * df;
    }

    __shared__ float sb[16];
    {
        float v0 = sx2, v1 = sq2, v2 = sd2;
        for (int o = 16; o > 0; o >>= 1) {
            v0 += __shfl_down_sync(0xffffffffu, v0, o);
            v1 += __shfl_down_sync(0xffffffffu, v1, o);
            v2 += __shfl_down_sync(0xffffffffu, v2, o);
        }
        int w = tid >> 5;
        if ((tid & 31) == 0) { sb[w] = v0; sb[4 + w] = v1; sb[8 + w] = v2; }
        __syncthreads();
        sx2 = sb[0] + sb[1] + sb[2] + sb[3];
        sq2 = sb[4] + sb[5] + sb[6] + sb[7];
        sd2 = sb[8] + sb[9] + sb[10] + sb[11];
        __syncthreads();
    }

    float ns = sqrtf(sx2), nt = sqrtf(sq2);
    float ins = 1.f / fmaxf(ns, EPSV);
    float inv_t = 1.f / fmaxf(nt, EPSV);

    float wv[4];
    float sw2 = 0.f, sxw = 0.f;
#pragma unroll
    for (int i = 0; i < 4; i++) {
        float w = xv[i] * ins + qv[i] * inv_t;
        wv[i] = w;
        sw2 += w * w;
        sxw += xv[i] * w;
    }
    {
        float v0 = sw2, v1 = sxw;
        for (int o = 16; o > 0; o >>= 1) {
            v0 += __shfl_down_sync(0xffffffffu, v0, o);
            v1 += __shfl_down_sync(0xffffffffu, v1, o);
        }
        int w = tid >> 5;
        if ((tid & 31) == 0) { sb[w] = v0; sb[4 + w] = v1; }
        __syncthreads();
        sw2 = sb[0] + sb[1] + sb[2] + sb[3];
        sxw = sb[4] + sb[5] + sb[6] + sb[7];
        __syncthreads();
    }

    float iwn = 1.f / fmaxf(sqrtf(sw2), EPSV);
    float xdw = sxw * iwn;
    float xdu = sx2 * ins;
    float scl = nt * ins;

    float* orow = out + (size_t)m * DIM;
#pragma unroll
    for (int i = 0; i < 4; i++) {
        int d = tid + i * 128;
        float r = xv[i] - 2.f * xdw * (wv[i] * iwn) + 2.f * xdu * (qv[i] * inv_t);
        orow[d] = r * scl;
    }

    if (tid == 0) {
        g_rowloss[m] = sd2;
        if (idx_off >= 0) out[idx_off + m] = (float)idx;
    }
}

__global__ void loss_k(float* __restrict__ out, int M, long long pos) {
    int tid = threadIdx.x;
    float s = 0.f;
    for (int i = tid; i < M; i += 256) s += g_rowloss[i];
    for (int o = 16; o > 0; o >>= 1) s += __shfl_down_sync(0xffffffffu, s, o);
    __shared__ float sb[8];
    if ((tid & 31) == 0) sb[tid >> 5] = s;
    __syncthreads();
    if (tid == 0) {
        float t = 0.f;
        for (int i = 0; i < 8; i++) t += sb[i];
        if (pos >= 0) out[pos] = 1.25f * t / (float)((size_t)M * DIM);
    }
}

// ---------------- host launcher ----------------
extern "C" void kernel_launch(void* const* d_in, const int* in_sizes, int n_in,
                              void* d_out, int out_size)
{
    const float* x  = (const float*)d_in[0];
    const float* cb = (const float*)d_in[1];
    const float* W1 = (const float*)d_in[2];
    const float* b1 = (const float*)d_in[3];
    const float* W2 = (const float*)d_in[4];
    const float* b2 = (const float*)d_in[5];
    float* out = (float*)d_out;

    int M = in_sizes[0] / DIM;
    long long NQ = (long long)M * DIM;

    long long idx_off = (out_size >= NQ + M) ? NQ : -1;
    long long loss_pos = -1;
    if (out_size >= NQ + M + 1) loss_pos = NQ + M;
    else if (out_size == NQ + 1) loss_pos = NQ;

    float *p_h, *p_icb, *p_ccpart;
    __nv_bfloat16 *p_chi;
    cudaGetSymbolAddress((void**)&p_h,      g_h);
    cudaGetSymbolAddress((void**)&p_icb,    g_icb);
    cudaGetSymbolAddress((void**)&p_ccpart, g_ccpart);
    cudaGetSymbolAddress((void**)&p_chi,    g_chi);

    cudaFuncSetAttribute(dist_mma_k, cudaFuncAttributeMaxDynamicSharedMemorySize, SM_TOTAL);

    cudaMemsetAsync(d_out, 0, (size_t)out_size * sizeof(float));

    // x prep (xx, xhi, state init)
    prep_x_k<<<M, 128>>>(x);

    // icb transform (fp32, fused bf16 + ||.||^2 epilogue on pass 2)
    gemm64x128_k<<<dim3(DIM / 128, CSIZE / 64), 256>>>(
        cb, W1, b1, nullptr, p_h, CSIZE, DIM, CDIM, 0, nullptr, nullptr);
    gemm64x128_k<<<dim3(DIM / 128, CSIZE / 64), 256>>>(
        p_h, W2, b2, p_h, p_icb, CSIZE, DIM, DIM, 1, p_chi, p_ccpart);
    ccfin_k<<<CSIZE / 256, 256>>>();

    // phase 1: approx distances + candidates
    dist_mma_k<<<dim3(CSIZE / NT, M / MT), 256, SM_TOTAL>>>();

    // phase 2 + finish
    refine_finish_k<<<M, 128>>>(x, out, M, idx_off);
    loss_k<<<1, 256>>>(out, M, loss_pos);
}

// round 7
// speedup vs baseline: 1.3059x; 1.1038x over previous
#include <cuda_runtime.h>
#include <cuda_bf16.h>
#include <cstdint>
#include <math.h>

#define DIM   512
#define CDIM  128
#define CSIZE 8192
#define MMAX  16384
#define EPSV  1e-6f
#define CAP   64

// ---- dist kernel tiling ----
#define MT 128
#define NT 128
#define KC 32
#define NSTAGES (DIM / KC)        // 16
#define ROWB 80                   // 32 bf16 = 64B + 16B pad
#define BUFSZ (128 * ROWB)        // 10240 B
#define OFF_AHI 0
#define OFF_BHI BUFSZ
#define SM_STAGE (2 * BUFSZ)      // 20480
#define SM_BUF0 1024              // cc tile
#define SM_TOTAL (SM_BUF0 + 2 * SM_STAGE)   // 41984

// ---------------- device scratch ----------------
__device__ float g_h[CSIZE * DIM];
__device__ float g_icb[CSIZE * DIM];
__device__ float g_cc[CSIZE];
__device__ float g_ccpart[4 * CSIZE];
__device__ float g_xx[MMAX];
__device__ float g_rowloss[MMAX];
__device__ __nv_bfloat16 g_xhi[MMAX * DIM];
__device__ __nv_bfloat16 g_chi[CSIZE * DIM];
__device__ unsigned int g_rowmin[MMAX];
__device__ unsigned int g_ccount[MMAX];
__device__ int g_cand[MMAX * CAP];
__device__ unsigned int g_maxcc_u;

// ---------------- helpers ----------------
__device__ __forceinline__ uint32_t smem_u32(const void* p) {
    uint32_t a;
    asm("{ .reg .u64 t; cvta.to.shared.u64 t, %1; cvt.u32.u64 %0, t; }"
        : "=r"(a) : "l"(p));
    return a;
}

#define CP_ASYNC16(dst, src) \
    asm volatile("cp.async.cg.shared.global [%0], [%1], 16;" :: "r"(dst), "l"(src))
#define CP_COMMIT() asm volatile("cp.async.commit_group;" ::: "memory")
#define CP_WAIT1() asm volatile("cp.async.wait_group 1;" ::: "memory")
#define CP_WAIT0() asm volatile("cp.async.wait_group 0;" ::: "memory")

__device__ __forceinline__ void ldm_x4(uint32_t* r, uint32_t addr) {
    asm volatile("ldmatrix.sync.aligned.m8n8.x4.shared.b16 {%0,%1,%2,%3}, [%4];"
                 : "=r"(r[0]), "=r"(r[1]), "=r"(r[2]), "=r"(r[3]) : "r"(addr));
}
__device__ __forceinline__ void mma_bf16(float* c, const uint32_t* a, const uint32_t* b) {
    asm volatile(
        "mma.sync.aligned.m16n8k16.row.col.f32.bf16.bf16.f32 "
        "{%0,%1,%2,%3}, {%4,%5,%6,%7}, {%8,%9}, {%0,%1,%2,%3};"
        : "+f"(c[0]), "+f"(c[1]), "+f"(c[2]), "+f"(c[3])
        : "r"(a[0]), "r"(a[1]), "r"(a[2]), "r"(a[3]), "r"(b[0]), "r"(b[1]));
}

__device__ __forceinline__ unsigned int ord_enc(float f) {
    unsigned int u = __float_as_uint(f);
    return (u & 0x80000000u) ? ~u : (u | 0x80000000u);
}
__device__ __forceinline__ float ord_dec(unsigned int e) {
    unsigned int u = (e & 0x80000000u) ? (e & 0x7fffffffu) : ~e;
    return __uint_as_float(u);
}

__device__ __forceinline__ float selu_f(float z) {
    const float a = 1.6732632423543772f;
    const float s = 1.0507009873554805f;
    return s * (z > 0.f ? z : a * expm1f(z));
}

// ---------------- prep_x: xx + xhi + init state ----------------
__global__ void prep_x_k(const float* __restrict__ X) {
    int m = blockIdx.x;
    int tid = threadIdx.x;     // 128
    const float* r = X + (size_t)m * DIM;
    __nv_bfloat16* ho = g_xhi + (size_t)m * DIM;
    float s = 0.f;
#pragma unroll
    for (int i = 0; i < 4; i++) {
        float v = r[tid + i * 128];
        s += v * v;
        ho[tid + i * 128] = __float2bfloat16(v);
    }
    for (int o = 16; o > 0; o >>= 1) s += __shfl_down_sync(0xffffffffu, s, o);
    __shared__ float sb[4];
    if ((tid & 31) == 0) sb[tid >> 5] = s;
    __syncthreads();
    if (tid == 0) {
        g_xx[m] = sb[0] + sb[1] + sb[2] + sb[3];
        g_rowmin[m] = 0xFFFFFFFFu;
        g_ccount[m] = 0u;
        if (m == 0) g_maxcc_u = 0u;
    }
}

// ---------------- 128x128 SGEMM: C = f(A)@B + bias (+ Ares) [+bf16 +cc] ----
__global__ void __launch_bounds__(256) gemm128_k(
    const float* __restrict__ A, const float* __restrict__ B,
    const float* __restrict__ bias, const float* __restrict__ Ares,
    float* __restrict__ C, int M, int N, int K, int doSelu,
    __nv_bfloat16* __restrict__ hiOut, float* __restrict__ ccpart)
{
    __shared__ float As[16][128];
    __shared__ float Bs[16][128];
    int tid = threadIdx.x;
    int tx = tid & 15, ty = tid >> 4;
    int m0 = blockIdx.y * 128, n0 = blockIdx.x * 128;

    int arow = tid >> 1, ak = (tid & 1) * 8;
    int brow = tid >> 4, bcol = (tid & 15) * 8;

    float acc[8][8];
#pragma unroll
    for (int i = 0; i < 8; i++)
#pragma unroll
        for (int j = 0; j < 8; j++) acc[i][j] = 0.f;

    for (int k0 = 0; k0 < K; k0 += 16) {
        float4 a0 = *(const float4*)(A + (size_t)(m0 + arow) * K + k0 + ak);
        float4 a1 = *(const float4*)(A + (size_t)(m0 + arow) * K + k0 + ak + 4);
        if (doSelu) {
            a0.x = selu_f(a0.x); a0.y = selu_f(a0.y); a0.z = selu_f(a0.z); a0.w = selu_f(a0.w);
            a1.x = selu_f(a1.x); a1.y = selu_f(a1.y); a1.z = selu_f(a1.z); a1.w = selu_f(a1.w);
        }
        As[ak + 0][arow] = a0.x; As[ak + 1][arow] = a0.y;
        As[ak + 2][arow] = a0.z; As[ak + 3][arow] = a0.w;
        As[ak + 4][arow] = a1.x; As[ak + 5][arow] = a1.y;
        As[ak + 6][arow] = a1.z; As[ak + 7][arow] = a1.w;

        float4 b0 = *(const float4*)(B + (size_t)(k0 + brow) * N + n0 + bcol);
        float4 b1 = *(const float4*)(B + (size_t)(k0 + brow) * N + n0 + bcol + 4);
        *(float4*)&Bs[brow][bcol] = b0;
        *(float4*)&Bs[brow][bcol + 4] = b1;
        __syncthreads();

#pragma unroll
        for (int k = 0; k < 16; k++) {
            float a[8], b[8];
#pragma unroll
            for (int i = 0; i < 8; i++) a[i] = As[k][ty * 8 + i];
#pragma unroll
            for (int j = 0; j < 8; j++) b[j] = Bs[k][tx * 8 + j];
#pragma unroll
            for (int i = 0; i < 8; i++)
#pragma unroll
                for (int j = 0; j < 8; j++) acc[i][j] += a[i] * b[j];
        }
        __syncthreads();
    }

    int part = n0 >> 7;
#pragma unroll
    for (int i = 0; i < 8; i++) {
        int m = m0 + ty * 8 + i;
        float s = 0.f;
#pragma unroll
        for (int j = 0; j < 8; j++) {
            int n = n0 + tx * 8 + j;
            float v = acc[i][j] + bias[n];
            if (Ares) v += Ares[(size_t)m * N + n];
            C[(size_t)m * N + n] = v;
            if (hiOut) hiOut[(size_t)m * N + n] = __float2bfloat16(v);
            s += v * v;
        }
        if (ccpart) {
#pragma unroll
            for (int o = 8; o > 0; o >>= 1)
                s += __shfl_down_sync(0xffffffffu, s, o, 16);
            if (tx == 0) ccpart[part * CSIZE + m] = s;
        }
    }
}

// ---------------- cc finalize: sum 4 parts + global max ----------------
__global__ void ccfin_k() {
    int i = blockIdx.x * 256 + threadIdx.x;
    float cc = ((g_ccpart[i] + g_ccpart[CSIZE + i]) + g_ccpart[2 * CSIZE + i])
               + g_ccpart[3 * CSIZE + i];
    g_cc[i] = cc;
    float mx = cc;
    for (int o = 16; o > 0; o >>= 1) mx = fmaxf(mx, __shfl_down_sync(0xffffffffu, mx, o));
    __shared__ float sb[8];
    int tid = threadIdx.x;
    if ((tid & 31) == 0) sb[tid >> 5] = mx;
    __syncthreads();
    if (tid == 0) {
        float t = sb[0];
#pragma unroll
        for (int k = 1; k < 8; k++) t = fmaxf(t, sb[k]);
        atomicMax(&g_maxcc_u, ord_enc(t));
    }
}

// ---------------- Phase 1: approx bf16 dist GEMM + candidate filter --------
// CTA 128x128, 8 warps of 32x64, 2-stage pipeline, paired-B ldmatrix.x4.
__global__ void __launch_bounds__(256) dist_mma_k() {
    extern __shared__ char smem[];
    uint32_t sbase = smem_u32(smem);
    float* s_cc = (float*)smem;

    int tid = threadIdx.x;
    int wid = tid >> 5, lane = tid & 31;
    int bn = blockIdx.x * NT;
    int bm = blockIdx.y * MT;

    int wm = (wid & 3) * 32;
    int wn = (wid >> 2) * 64;

    if (tid < NT) s_cc[tid] = g_cc[bn + tid];
    float maxcc = ord_dec(g_maxcc_u);

    float acc[2][8][4];
#pragma unroll
    for (int i = 0; i < 2; i++)
#pragma unroll
        for (int j = 0; j < 8; j++)
#pragma unroll
            for (int r = 0; r < 4; r++) acc[i][j][r] = 0.f;

    const __nv_bfloat16* xhi = g_xhi;
    const __nv_bfloat16* chi = g_chi;

    auto issue_stage = [&](int s) {
        int b = s & 1;
        int k0 = s * KC;
        uint32_t buf = sbase + SM_BUF0 + b * SM_STAGE;
#pragma unroll
        for (int r = 0; r < 2; r++) {
            int c = tid + 256 * r;
            int row = c >> 2, part = c & 3;
            uint32_t so = (uint32_t)(row * ROWB + part * 16);
            size_t goA = (size_t)(bm + row) * DIM + k0 + part * 8;
            size_t goB = (size_t)(bn + row) * DIM + k0 + part * 8;
            CP_ASYNC16(buf + OFF_AHI + so, xhi + goA);
            CP_ASYNC16(buf + OFF_BHI + so, chi + goB);
        }
    };

    issue_stage(0);
    CP_COMMIT();

    for (int s = 0; s < NSTAGES; s++) {
        if (s + 1 < NSTAGES) {
            issue_stage(s + 1);
            CP_COMMIT();
            CP_WAIT1();
        } else {
            CP_WAIT0();
        }
        __syncthreads();

        uint32_t buf = sbase + SM_BUF0 + (s & 1) * SM_STAGE;
        int g = lane >> 3;          // 8-lane group 0..3
#pragma unroll
        for (int kk = 0; kk < 2; kk++) {
            int kb = kk * 32;
            uint32_t arow = (uint32_t)((wm + (lane & 15)) * ROWB + kb + (lane >> 4) * 16);
            uint32_t ahi0[4], ahi1[4];
            ldm_x4(ahi0, buf + OFF_AHI + arow);
            ldm_x4(ahi1, buf + OFF_AHI + arow + 16 * ROWB);

            // Paired B: one ldm_x4 = two j-groups x two k-halves.
            // lanes 0-7 -> (j, k-lo), 8-15 -> (j, k-hi),
            // 16-23 -> (j+1, k-lo), 24-31 -> (j+1, k-hi)
            uint32_t baddr_base = (uint32_t)((wn + (g >> 1) * 8 + (lane & 7)) * ROWB
                                             + kb + (g & 1) * 16);
#pragma unroll
            for (int jp = 0; jp < 4; jp++) {
                uint32_t bfrag[4];
                ldm_x4(bfrag, buf + OFF_BHI + baddr_base + (uint32_t)(jp * 16 * ROWB));
                mma_bf16(acc[0][2 * jp + 0], ahi0, bfrag + 0);
                mma_bf16(acc[0][2 * jp + 1], ahi0, bfrag + 2);
                mma_bf16(acc[1][2 * jp + 0], ahi1, bfrag + 0);
                mma_bf16(acc[1][2 * jp + 1], ahi1, bfrag + 2);
            }
        }
        __syncthreads();
    }

    // -------- epilogue: approx d2, running rowmin, candidate push --------
    int q = lane >> 2, t = lane & 3;
#pragma unroll
    for (int i = 0; i < 2; i++) {
#pragma unroll
        for (int h = 0; h < 2; h++) {
            int row = bm + wm + i * 16 + h * 8 + q;
            float xxv = g_xx[row];
            float d2s[16];
            float best = 3.4e38f;
#pragma unroll
            for (int j = 0; j < 8; j++) {
#pragma unroll
                for (int e = 0; e < 2; e++) {
                    float dot = acc[i][j][h * 2 + e];
                    float d2 = __fadd_rn(__fadd_rn(xxv, __fmul_rn(dot, -2.0f)),
                                         s_cc[wn + j * 8 + 2 * t + e]);
                    d2s[j * 2 + e] = d2;
                    best = fminf(best, d2);
                }
            }
            unsigned int fb = ord_enc(best);
            unsigned int o1 = __shfl_xor_sync(0xffffffffu, fb, 1);
            fb = (o1 < fb) ? o1 : fb;
            unsigned int o2 = __shfl_xor_sync(0xffffffffu, fb, 2);
            fb = (o2 < fb) ? o2 : fb;
            unsigned int old = 0xFFFFFFFFu;
            if (t == 0) old = atomicMin(&g_rowmin[row], fb);
            old = __shfl_sync(0xffffffffu, old, lane & ~3);
            unsigned int run = (old < fb) ? old : fb;
            float thr = ord_dec(run) + (2.f * sqrtf(xxv * maxcc) * 0.0078125f + 0.01f);
#pragma unroll
            for (int j = 0; j < 8; j++) {
#pragma unroll
                for (int e = 0; e < 2; e++) {
                    if (d2s[j * 2 + e] < thr) {
                        unsigned int slot = atomicAdd(&g_ccount[row], 1u);
                        if (slot < CAP)
                            g_cand[row * CAP + slot] = bn + wn + j * 8 + 2 * t + e;
                    }
                }
            }
        }
    }
}

// ---------------- Phase 2 + finish: exact refine, rotation, loss -----------
__global__ void refine_finish_k(const float* __restrict__ X, float* __restrict__ out,
                                int M, long long idx_off)
{
    int m = blockIdx.x;
    int tid = threadIdx.x;   // 128
    unsigned int cnt = g_ccount[m];
    float xxv = g_xx[m];
    const float* xr = X + (size_t)m * DIM;

    float xv[4];
#pragma unroll
    for (int i = 0; i < 4; i++) xv[i] = xr[tid + i * 128];

    __shared__ float sred[4];
    __shared__ unsigned long long s_best;
    __shared__ int s_idx;
    if (tid == 0) s_best = ~0ULL;
    __syncthreads();

    bool fullscan = (cnt == 0u) || (cnt > (unsigned)CAP);
    int n_iter = fullscan ? CSIZE : (int)cnt;

    for (int s = 0; s < n_iter; s++) {
        int c = fullscan ? s : g_cand[m * CAP + s];
        const float* cr = g_icb + (size_t)c * DIM;
        float p = 0.f;
#pragma unroll
        for (int i = 0; i < 4; i++) p += xv[i] * cr[tid + i * 128];
        for (int o = 16; o > 0; o >>= 1) p += __shfl_down_sync(0xffffffffu, p, o);
        if ((tid & 31) == 0) sred[tid >> 5] = p;
        __syncthreads();
        if (tid == 0) {
            float dot = sred[0] + sred[1] + sred[2] + sred[3];
            float d2 = __fadd_rn(__fadd_rn(xxv, __fmul_rn(dot, -2.0f)), g_cc[c]);
            unsigned long long key =
                ((unsigned long long)ord_enc(d2) << 32) | (unsigned)c;
            if (key < s_best) s_best = key;
        }
        __syncthreads();
    }
    if (tid == 0) s_idx = (int)(s_best & 0xffffffffu);
    __syncthreads();
    int idx = s_idx;

    // ---- rotation + loss ----
    const float* qr = g_icb + (size_t)idx * DIM;
    float qv[4];
    float sx2 = 0.f, sq2 = 0.f, sd2 = 0.f;
#pragma unroll
    for (int i = 0; i < 4; i++) {
        int d = tid + i * 128;
        qv[i] = qr[d];
        sx2 += xv[i] * xv[i];
        sq2 += qv[i] * qv[i];
        float df = xv[i] - qv[i];
        sd2 += df * df;
    }

    __shared__ float sb[16];
    {
        float v0 = sx2, v1 = sq2, v2 = sd2;
        for (int o = 16; o > 0; o >>= 1) {
            v0 += __shfl_down_sync(0xffffffffu, v0, o);
            v1 += __shfl_down_sync(0xffffffffu, v1, o);
            v2 += __shfl_down_sync(0xffffffffu, v2, o);
        }
        int w = tid >> 5;
        if ((tid & 31) == 0) { sb[w] = v0; sb[4 + w] = v1; sb[8 + w] = v2; }
        __syncthreads();
        sx2 = sb[0] + sb[1] + sb[2] + sb[3];
        sq2 = sb[4] + sb[5] + sb[6] + sb[7];
        sd2 = sb[8] + sb[9] + sb[10] + sb[11];
        __syncthreads();
    }

    float ns = sqrtf(sx2), nt = sqrtf(sq2);
    float ins = 1.f / fmaxf(ns, EPSV);
    float inv_t = 1.f / fmaxf(nt, EPSV);

    float wv[4];
    float sw2 = 0.f, sxw = 0.f;
#pragma unroll
    for (int i = 0; i < 4; i++) {
        float w = xv[i] * ins + qv[i] * inv_t;
        wv[i] = w;
        sw2 += w * w;
        sxw += xv[i] * w;
    }
    {
        float v0 = sw2, v1 = sxw;
        for (int o = 16; o > 0; o >>= 1) {
            v0 += __shfl_down_sync(0xffffffffu, v0, o);
            v1 += __shfl_down_sync(0xffffffffu, v1, o);
        }
        int w = tid >> 5;
        if ((tid & 31) == 0) { sb[w] = v0; sb[4 + w] = v1; }
        __syncthreads();
        sw2 = sb[0] + sb[1] + sb[2] + sb[3];
        sxw = sb[4] + sb[5] + sb[6] + sb[7];
        __syncthreads();
    }

    float iwn = 1.f / fmaxf(sqrtf(sw2), EPSV);
    float xdw = sxw * iwn;
    float xdu = sx2 * ins;
    float scl = nt * ins;

    float* orow = out + (size_t)m * DIM;
#pragma unroll
    for (int i = 0; i < 4; i++) {
        int d = tid + i * 128;
        float r = xv[i] - 2.f * xdw * (wv[i] * iwn) + 2.f * xdu * (qv[i] * inv_t);
        orow[d] = r * scl;
    }

    if (tid == 0) {
        g_rowloss[m] = sd2;
        if (idx_off >= 0) out[idx_off + m] = (float)idx;
    }
}

__global__ void loss_k(float* __restrict__ out, int M, long long pos) {
    int tid = threadIdx.x;
    float s = 0.f;
    for (int i = tid; i < M; i += 256) s += g_rowloss[i];
    for (int o = 16; o > 0; o >>= 1) s += __shfl_down_sync(0xffffffffu, s, o);
    __shared__ float sb[8];
    if ((tid & 31) == 0) sb[tid >> 5] = s;
    __syncthreads();
    if (tid == 0) {
        float t = 0.f;
        for (int i = 0; i < 8; i++) t += sb[i];
        if (pos >= 0) out[pos] = 1.25f * t / (float)((size_t)M * DIM);
    }
}

// ---------------- host launcher ----------------
extern "C" void kernel_launch(void* const* d_in, const int* in_sizes, int n_in,
                              void* d_out, int out_size)
{
    const float* x  = (const float*)d_in[0];
    const float* cb = (const float*)d_in[1];
    const float* W1 = (const float*)d_in[2];
    const float* b1 = (const float*)d_in[3];
    const float* W2 = (const float*)d_in[4];
    const float* b2 = (const float*)d_in[5];
    float* out = (float*)d_out;

    int M = in_sizes[0] / DIM;
    long long NQ = (long long)M * DIM;

    long long idx_off = (out_size >= NQ + M) ? NQ : -1;
    long long loss_pos = -1;
    if (out_size >= NQ + M + 1) loss_pos = NQ + M;
    else if (out_size == NQ + 1) loss_pos = NQ;

    float *p_h, *p_icb, *p_ccpart;
    __nv_bfloat16 *p_chi;
    cudaGetSymbolAddress((void**)&p_h,      g_h);
    cudaGetSymbolAddress((void**)&p_icb,    g_icb);
    cudaGetSymbolAddress((void**)&p_ccpart, g_ccpart);
    cudaGetSymbolAddress((void**)&p_chi,    g_chi);

    cudaFuncSetAttribute(dist_mma_k, cudaFuncAttributeMaxDynamicSharedMemorySize, SM_TOTAL);

    cudaMemsetAsync(d_out, 0, (size_t)out_size * sizeof(float));

    // x prep (xx, xhi, state init)
    prep_x_k<<<M, 128>>>(x);

    // icb transform (128x128 tiles; fused bf16 + ||.||^2 epilogue on pass 2)
    gemm128_k<<<dim3(DIM / 128, CSIZE / 128), 256>>>(
        cb, W1, b1, nullptr, p_h, CSIZE, DIM, CDIM, 0, nullptr, nullptr);
    gemm128_k<<<dim3(DIM / 128, CSIZE / 128), 256>>>(
        p_h, W2, b2, p_h, p_icb, CSIZE, DIM, DIM, 1, p_chi, p_ccpart);
    ccfin_k<<<CSIZE / 256, 256>>>();

    // phase 1: approx distances + candidates
    dist_mma_k<<<dim3(CSIZE / NT, M / MT), 256, SM_TOTAL>>>();

    // phase 2 + finish
    refine_finish_k<<<M, 128>>>(x, out, M, idx_off);
    loss_k<<<1, 256>>>(out, M, loss_pos);
}